// round 5
// baseline (speedup 1.0000x reference)
#include <cuda_runtime.h>

#define DD     64
#define NUSERS 100000
#define NENT   100000
#define NNODES 200000
#define EKG    1500000
#define EPREF  1500000
#define NNZK   1000000

// Scratch (no allocations allowed) — device globals.
__device__ float g_entA[(size_t)NENT * DD];
__device__ float g_entB[(size_t)NENT * DD];
__device__ float g_nodeA[(size_t)NNODES * DD];
__device__ float g_nodeB[(size_t)NNODES * DD];
__device__ float g_uacc[(size_t)NUSERS * DD];
__device__ int   g_cntE[NENT];
__device__ int   g_cntN[NNODES];

// ---------------------------------------------------------------------------
// Fused scatter over KG edges (-> entity table) and preference edges
// (-> node table). 8 threads per edge, 2 independent float4 each (MLP=2).
// Edge e < EKG:   entOut[head]  += ent[tail] * w[etype-1];  cntE[head]++
// Edge e >= EKG:  nodeOut[ehead] += src[etail] * xw[xtype]; cntN[ehead]++
//   where src = node user-part if etail < NUSERS else entity table.
// ---------------------------------------------------------------------------
__global__ __launch_bounds__(256) void scatter_all_k(
    const float* __restrict__ ent, const float* __restrict__ userpart,
    const int* __restrict__ head, const int* __restrict__ tail,
    const int* __restrict__ etype, const float* __restrict__ w,
    const int* __restrict__ ehead, const int* __restrict__ etail,
    const int* __restrict__ xetype, const float* __restrict__ xw,
    float* __restrict__ entOut, int* __restrict__ cntE,
    float* __restrict__ nodeOut, int* __restrict__ cntN)
{
    unsigned tid = blockIdx.x * 256u + threadIdx.x;
    if (tid >= (unsigned)(EKG + EPREF) * 8u) return;
    unsigned e = tid >> 3, c = tid & 7u;

    const float* src; const float* wr; float* dst; int* cnt; int h;
    if (e < EKG) {
        h = head[e];
        int t = tail[e], r = etype[e] - 1;
        src = ent + (size_t)t * DD;
        wr  = w + (size_t)r * DD;
        dst = entOut; cnt = cntE;
    } else {
        unsigned e2 = e - EKG;
        h = ehead[e2];
        int t = etail[e2], r = xetype[e2];
        src = (t < NUSERS) ? (userpart + (size_t)t * DD)
                           : (ent + (size_t)(t - NUSERS) * DD);
        wr  = xw + (size_t)r * DD;
        dst = nodeOut; cnt = cntN;
    }

    float4 v0 = reinterpret_cast<const float4*>(src)[c];
    float4 v1 = reinterpret_cast<const float4*>(src)[c + 8];
    float4 w0 = reinterpret_cast<const float4*>(wr)[c];
    float4 w1 = reinterpret_cast<const float4*>(wr)[c + 8];
    v0.x *= w0.x; v0.y *= w0.y; v0.z *= w0.z; v0.w *= w0.w;
    v1.x *= w1.x; v1.y *= w1.y; v1.z *= w1.z; v1.w *= w1.w;

    float4* drow = reinterpret_cast<float4*>(dst + (size_t)h * DD);
    atomicAdd(drow + c, v0);
    atomicAdd(drow + c + 8, v1);
    if (c == 0) atomicAdd(cnt + h, 1);
}

// ---------------------------------------------------------------------------
// Interact: uacc[rows] += vals * entSum[cols] / cnt[cols]   (mean folded in)
// 8 threads per edge, 2 float4 each.
// ---------------------------------------------------------------------------
__global__ __launch_bounds__(256) void interact_k(
    const float* __restrict__ entSum, const int* __restrict__ cntE,
    const int* __restrict__ rows, const int* __restrict__ cols,
    const float* __restrict__ vals, float* __restrict__ uacc)
{
    unsigned tid = blockIdx.x * 256u + threadIdx.x;
    if (tid >= (unsigned)NNZK * 8u) return;
    unsigned e = tid >> 3, c = tid & 7u;
    int r = rows[e], col = cols[e];
    float s = vals[e] / fmaxf((float)cntE[col], 1.f);

    const float4* srow = reinterpret_cast<const float4*>(entSum + (size_t)col * DD);
    float4 v0 = srow[c];
    float4 v1 = srow[c + 8];
    v0.x *= s; v0.y *= s; v0.z *= s; v0.w *= s;
    v1.x *= s; v1.y *= s; v1.z *= s; v1.w *= s;

    float4* drow = reinterpret_cast<float4*>(uacc + (size_t)r * DD);
    atomicAdd(drow + c, v0);
    atomicAdd(drow + c + 8, v1);
}

// ---------------------------------------------------------------------------
// Fused finalize over entity (mean+norm, optional copy-out), node
// (mean+norm+residual) and user (norm+residual) tables.
// One warp per row, 32 lanes x float2.
// ---------------------------------------------------------------------------
__global__ __launch_bounds__(256) void finalize_all_k(
    float* __restrict__ entBuf, const int* __restrict__ cntE,
    float* __restrict__ entCopy,               // last hop: gcn_res entity slice
    float* __restrict__ nodeBuf, const int* __restrict__ cntN,
    float* __restrict__ nodeRes,
    float* __restrict__ uaccBuf, float* __restrict__ userRes)
{
    int idx = blockIdx.x * 8 + (int)(threadIdx.x >> 5);
    int lane = threadIdx.x & 31;
    const int TOT = NENT + NNODES + NUSERS;
    if (idx >= TOT) return;

    float* buf; const int* cnt; float* res; float* cpy;
    if (idx < NENT) {
        buf = entBuf + (size_t)idx * DD; cnt = cntE + idx;
        res = nullptr;
        cpy = entCopy ? entCopy + (size_t)idx * DD : nullptr;
    } else if (idx < NENT + NNODES) {
        int r = idx - NENT;
        buf = nodeBuf + (size_t)r * DD; cnt = cntN + r;
        res = nodeRes + (size_t)r * DD; cpy = nullptr;
    } else {
        int r = idx - NENT - NNODES;
        buf = uaccBuf + (size_t)r * DD; cnt = nullptr;
        res = userRes + (size_t)r * DD; cpy = nullptr;
    }

    float2* p = reinterpret_cast<float2*>(buf) + lane;
    float2 v = *p;
    if (cnt) {
        float inv = 1.f / fmaxf((float)(*cnt), 1.f);
        v.x *= inv; v.y *= inv;
    }
    float ss = v.x * v.x + v.y * v.y;
    #pragma unroll
    for (int o = 16; o > 0; o >>= 1) ss += __shfl_xor_sync(0xffffffffu, ss, o);
    float inv = 1.f / fmaxf(sqrtf(ss), 1e-12f);
    v.x *= inv; v.y *= inv;
    *p = v;
    if (res) {
        float2* q = reinterpret_cast<float2*>(res) + lane;
        float2 r = *q; r.x += v.x; r.y += v.y; *q = r;
    }
    if (cpy)
        reinterpret_cast<float2*>(cpy)[lane] = v;
}

// ---------------------------------------------------------------------------
extern "C" void kernel_launch(void* const* d_in, const int* in_sizes, int n_in,
                              void* d_out, int out_size)
{
    (void)in_sizes; (void)n_in; (void)out_size;
    const float* user_emb   = (const float*)d_in[0];
    const float* entity_emb = (const float*)d_in[1];
    const float* weight     = (const float*)d_in[2];
    const float* exweight   = (const float*)d_in[3];
    const float* ivals      = (const float*)d_in[4];
    const int*   eidx       = (const int*)d_in[5];
    const int*   etype      = (const int*)d_in[6];
    const int*   xeidx      = (const int*)d_in[7];
    const int*   xetype     = (const int*)d_in[8];
    const int*   iidx       = (const int*)d_in[9];
    float* out = (float*)d_out;

    const int* head  = eidx;
    const int* tail  = eidx + EKG;
    const int* ehead = xeidx;
    const int* etail = xeidx + EPREF;
    const int* rows  = iidx;
    const int* cols  = iidx + NNZK;

    float *entA, *entB, *nodeA, *nodeB, *uacc;
    int *cntE, *cntN;
    cudaGetSymbolAddress((void**)&entA,  g_entA);
    cudaGetSymbolAddress((void**)&entB,  g_entB);
    cudaGetSymbolAddress((void**)&nodeA, g_nodeA);
    cudaGetSymbolAddress((void**)&nodeB, g_nodeB);
    cudaGetSymbolAddress((void**)&uacc,  g_uacc);
    cudaGetSymbolAddress((void**)&cntE,  g_cntE);
    cudaGetSymbolAddress((void**)&cntN,  g_cntN);

    // Output layout: gcn_res = [user_res ; ent_final], then node_res.
    float* user_res = out;                                   // NUSERS*DD
    float* ent_out  = out + (size_t)NUSERS * DD;             // NENT*DD
    float* node_res = out + (size_t)(NUSERS + NENT) * DD;    // NNODES*DD

    // Residual initialization (fully rewrites all d_out regions each replay).
    cudaMemcpyAsync(user_res, user_emb, sizeof(float) * (size_t)NUSERS * DD,
                    cudaMemcpyDeviceToDevice);
    cudaMemcpyAsync(node_res, user_emb, sizeof(float) * (size_t)NUSERS * DD,
                    cudaMemcpyDeviceToDevice);
    cudaMemcpyAsync(node_res + (size_t)NUSERS * DD, entity_emb,
                    sizeof(float) * (size_t)NENT * DD, cudaMemcpyDeviceToDevice);

    const float* entCur   = entity_emb;  // entity table read this hop
    const float* userPart = user_emb;    // user slice of node table read this hop
    float* entNext  = entA;
    float* nodeNext = nodeA;

    const int B = 256;
    const int SCAT_GRID = (int)(((size_t)(EKG + EPREF) * 8 + B - 1) / B);
    const int INT_GRID  = (int)(((size_t)NNZK * 8 + B - 1) / B);
    const int FIN_GRID  = (NENT + NNODES + NUSERS + 7) / 8;

    for (int hop = 0; hop < 2; hop++) {
        cudaMemsetAsync(entNext,  0, sizeof(float) * (size_t)NENT * DD);
        cudaMemsetAsync(nodeNext, 0, sizeof(float) * (size_t)NNODES * DD);
        cudaMemsetAsync(uacc,     0, sizeof(float) * (size_t)NUSERS * DD);
        cudaMemsetAsync(cntE,     0, sizeof(int) * NENT);
        cudaMemsetAsync(cntN,     0, sizeof(int) * NNODES);

        scatter_all_k<<<SCAT_GRID, B>>>(
            entCur, userPart, head, tail, etype, weight,
            ehead, etail, xetype, exweight,
            entNext, cntE, nodeNext, cntN);

        interact_k<<<INT_GRID, B>>>(entNext, cntE, rows, cols, ivals, uacc);

        finalize_all_k<<<FIN_GRID, B>>>(
            entNext, cntE, (hop == 1) ? ent_out : nullptr,
            nodeNext, cntN, node_res,
            uacc, user_res);

        entCur   = entNext;
        userPart = nodeNext;   // next hop's user slice = normalized node table
        entNext  = entB;
        nodeNext = nodeB;
    }
}

// round 8
// speedup vs baseline: 1.2277x; 1.2277x over previous
#include <cuda_runtime.h>

#define DD     64
#define NUSERS 100000
#define NENT   100000
#define NNODES 200000
#define EKG    1500000
#define EPREF  1500000
#define NNZK   1000000

// Scratch (no allocations allowed) — device globals.
__device__ float g_entA[(size_t)NENT * DD];
__device__ float g_entB[(size_t)NENT * DD];
__device__ float g_nodeA[(size_t)NNODES * DD];
__device__ float g_nodeB[(size_t)NNODES * DD];
__device__ float g_uacc[(size_t)NUSERS * DD];
__device__ int   g_cntE[NENT];
__device__ int   g_cntN[NNODES];

// ---------------------------------------------------------------------------
// KG edges: out[head] += ent[tail] * weight[etype-1]; cnt[head] += 1
// 16 threads per edge, one float4 each (R3 shape — L1tex-friendly).
// ---------------------------------------------------------------------------
__global__ __launch_bounds__(256) void kg_scatter_k(
    const float* __restrict__ ent, const int* __restrict__ head,
    const int* __restrict__ tail, const int* __restrict__ etype,
    const float* __restrict__ w, float* __restrict__ out, int* __restrict__ cnt)
{
    unsigned tid = blockIdx.x * 256u + threadIdx.x;
    if (tid >= (unsigned)EKG * 16u) return;
    unsigned e = tid >> 4, c = tid & 15u;
    int h = head[e], t = tail[e], r = etype[e] - 1;
    float4 v  = reinterpret_cast<const float4*>(ent + (size_t)t * DD)[c];
    float4 ww = reinterpret_cast<const float4*>(w + (size_t)r * DD)[c];
    v.x *= ww.x; v.y *= ww.y; v.z *= ww.z; v.w *= ww.w;
    atomicAdd(reinterpret_cast<float4*>(out + (size_t)h * DD) + c, v);
    if (c == 0) atomicAdd(cnt + h, 1);
}

// ---------------------------------------------------------------------------
// Preference edges: src row comes from user-part (node table) or entity table.
// ---------------------------------------------------------------------------
__global__ __launch_bounds__(256) void pref_scatter_k(
    const float* __restrict__ userpart, const float* __restrict__ entpart,
    const int* __restrict__ ehead, const int* __restrict__ etail,
    const int* __restrict__ etype, const float* __restrict__ w,
    float* __restrict__ out, int* __restrict__ cnt)
{
    unsigned tid = blockIdx.x * 256u + threadIdx.x;
    if (tid >= (unsigned)EPREF * 16u) return;
    unsigned e = tid >> 4, c = tid & 15u;
    int h = ehead[e], t = etail[e], r = etype[e];
    const float* src = (t < NUSERS) ? (userpart + (size_t)t * DD)
                                    : (entpart + (size_t)(t - NUSERS) * DD);
    float4 v  = reinterpret_cast<const float4*>(src)[c];
    float4 ww = reinterpret_cast<const float4*>(w + (size_t)r * DD)[c];
    v.x *= ww.x; v.y *= ww.y; v.z *= ww.z; v.w *= ww.w;
    atomicAdd(reinterpret_cast<float4*>(out + (size_t)h * DD) + c, v);
    if (c == 0) atomicAdd(cnt + h, 1);
}

// ---------------------------------------------------------------------------
// Interact: uacc[rows] += vals * entSum[cols] / cnt[cols]  (mean folded in).
// 16 threads per edge, one float4 each.
// ---------------------------------------------------------------------------
__global__ __launch_bounds__(256) void interact_k(
    const float* __restrict__ entSum, const int* __restrict__ cntE,
    const int* __restrict__ rows, const int* __restrict__ cols,
    const float* __restrict__ vals, float* __restrict__ uacc)
{
    unsigned tid = blockIdx.x * 256u + threadIdx.x;
    if (tid >= (unsigned)NNZK * 16u) return;
    unsigned e = tid >> 4, c = tid & 15u;
    int r = rows[e], col = cols[e];
    float s = vals[e] / fmaxf((float)cntE[col], 1.f);
    float4 v = reinterpret_cast<const float4*>(entSum + (size_t)col * DD)[c];
    v.x *= s; v.y *= s; v.z *= s; v.w *= s;
    atomicAdd(reinterpret_cast<float4*>(uacc + (size_t)r * DD) + c, v);
}

// ---------------------------------------------------------------------------
// Fused finalize over entity (mean+norm, optional copy-out), node
// (mean+norm+residual) and user (norm+residual) tables.
// Residual: resOut[row] = resBase[row] + v.  On hop 0 resBase is the original
// embedding (removes the init memcpys); on hop 1 resBase == resOut (in-place).
// One warp per row, 32 lanes x float2.
// ---------------------------------------------------------------------------
__global__ __launch_bounds__(256) void finalize_all_k(
    float* __restrict__ entBuf, const int* __restrict__ cntE,
    float* __restrict__ entCopy,                    // last hop: gcn_res ent slice
    float* __restrict__ nodeBuf, const int* __restrict__ cntN,
    const float* __restrict__ nodeBaseU,            // node residual base, user part
    const float* __restrict__ nodeBaseE,            // node residual base, ent part
    float* __restrict__ nodeRes,
    float* __restrict__ uaccBuf,
    const float* __restrict__ userBase, float* __restrict__ userRes)
{
    int idx = blockIdx.x * 8 + (int)(threadIdx.x >> 5);
    int lane = threadIdx.x & 31;
    const int TOT = NENT + NNODES + NUSERS;
    if (idx >= TOT) return;

    float* buf; const int* cnt; const float* base; float* res; float* cpy;
    if (idx < NENT) {
        buf = entBuf + (size_t)idx * DD; cnt = cntE + idx;
        base = nullptr; res = nullptr;
        cpy = entCopy ? entCopy + (size_t)idx * DD : nullptr;
    } else if (idx < NENT + NNODES) {
        int r = idx - NENT;
        buf = nodeBuf + (size_t)r * DD; cnt = cntN + r;
        base = (r < NUSERS) ? nodeBaseU + (size_t)r * DD
                            : nodeBaseE + (size_t)(r - NUSERS) * DD;
        res = nodeRes + (size_t)r * DD; cpy = nullptr;
    } else {
        int r = idx - NENT - NNODES;
        buf = uaccBuf + (size_t)r * DD; cnt = nullptr;
        base = userBase + (size_t)r * DD;
        res = userRes + (size_t)r * DD; cpy = nullptr;
    }

    float2* p = reinterpret_cast<float2*>(buf) + lane;
    float2 v = *p;
    if (cnt) {
        float inv = 1.f / fmaxf((float)(*cnt), 1.f);
        v.x *= inv; v.y *= inv;
    }
    float ss = v.x * v.x + v.y * v.y;
    #pragma unroll
    for (int o = 16; o > 0; o >>= 1) ss += __shfl_xor_sync(0xffffffffu, ss, o);
    float inv = 1.f / fmaxf(sqrtf(ss), 1e-12f);
    v.x *= inv; v.y *= inv;
    *p = v;
    if (res) {
        float2 b = reinterpret_cast<const float2*>(base)[lane];
        b.x += v.x; b.y += v.y;
        reinterpret_cast<float2*>(res)[lane] = b;
    }
    if (cpy)
        reinterpret_cast<float2*>(cpy)[lane] = v;
}

// ---------------------------------------------------------------------------
extern "C" void kernel_launch(void* const* d_in, const int* in_sizes, int n_in,
                              void* d_out, int out_size)
{
    (void)in_sizes; (void)n_in; (void)out_size;
    const float* user_emb   = (const float*)d_in[0];
    const float* entity_emb = (const float*)d_in[1];
    const float* weight     = (const float*)d_in[2];
    const float* exweight   = (const float*)d_in[3];
    const float* ivals      = (const float*)d_in[4];
    const int*   eidx       = (const int*)d_in[5];
    const int*   etype      = (const int*)d_in[6];
    const int*   xeidx      = (const int*)d_in[7];
    const int*   xetype     = (const int*)d_in[8];
    const int*   iidx       = (const int*)d_in[9];
    float* out = (float*)d_out;

    const int* head  = eidx;
    const int* tail  = eidx + EKG;
    const int* ehead = xeidx;
    const int* etail = xeidx + EPREF;
    const int* rows  = iidx;
    const int* cols  = iidx + NNZK;

    float *entA, *entB, *nodeA, *nodeB, *uacc;
    int *cntE, *cntN;
    cudaGetSymbolAddress((void**)&entA,  g_entA);
    cudaGetSymbolAddress((void**)&entB,  g_entB);
    cudaGetSymbolAddress((void**)&nodeA, g_nodeA);
    cudaGetSymbolAddress((void**)&nodeB, g_nodeB);
    cudaGetSymbolAddress((void**)&uacc,  g_uacc);
    cudaGetSymbolAddress((void**)&cntE,  g_cntE);
    cudaGetSymbolAddress((void**)&cntN,  g_cntN);

    // Output layout: gcn_res = [user_res ; ent_final], then node_res.
    float* user_res = out;                                   // NUSERS*DD
    float* ent_out  = out + (size_t)NUSERS * DD;             // NENT*DD
    float* node_res = out + (size_t)(NUSERS + NENT) * DD;    // NNODES*DD

    const float* entCur   = entity_emb;  // entity table read this hop
    const float* userPart = user_emb;    // user slice of node table read this hop
    float* entNext  = entA;
    float* nodeNext = nodeA;

    const int B = 256;
    const int KG_GRID  = (int)(((size_t)EKG * 16 + B - 1) / B);
    const int PR_GRID  = (int)(((size_t)EPREF * 16 + B - 1) / B);
    const int INT_GRID = (int)(((size_t)NNZK * 16 + B - 1) / B);
    const int FIN_GRID = (NENT + NNODES + NUSERS + 7) / 8;

    for (int hop = 0; hop < 2; hop++) {
        cudaMemsetAsync(entNext,  0, sizeof(float) * (size_t)NENT * DD);
        cudaMemsetAsync(nodeNext, 0, sizeof(float) * (size_t)NNODES * DD);
        cudaMemsetAsync(uacc,     0, sizeof(float) * (size_t)NUSERS * DD);
        cudaMemsetAsync(cntE,     0, sizeof(int) * NENT);
        cudaMemsetAsync(cntN,     0, sizeof(int) * NNODES);

        kg_scatter_k<<<KG_GRID, B>>>(
            entCur, head, tail, etype, weight, entNext, cntE);
        pref_scatter_k<<<PR_GRID, B>>>(
            userPart, entCur, ehead, etail, xetype, exweight, nodeNext, cntN);
        interact_k<<<INT_GRID, B>>>(entNext, cntE, rows, cols, ivals, uacc);

        // hop 0: residual base = original embeddings; hop 1: in-place on d_out.
        const float* nbU = (hop == 0) ? user_emb   : node_res;
        const float* nbE = (hop == 0) ? entity_emb : node_res + (size_t)NUSERS * DD;
        const float* ubB = (hop == 0) ? user_emb   : user_res;

        finalize_all_k<<<FIN_GRID, B>>>(
            entNext, cntE, (hop == 1) ? ent_out : nullptr,
            nodeNext, cntN, nbU, nbE, node_res,
            uacc, ubB, user_res);

        entCur   = entNext;
        userPart = nodeNext;   // next hop's user slice = normalized node table
        entNext  = entB;
        nodeNext = nodeB;
    }
}